// round 1
// baseline (speedup 1.0000x reference)
#include <cuda_runtime.h>
#include <math.h>

#define Hc   1024
#define Nst  64
#define Lt   4096
#define OUTc 512
#define BSz  2
#define CH3  342   // per-axis posenc channels

// ---------------- scratch (device globals; no allocation allowed) ----------------
__device__ float g_v [BSz*Hc*Lt];     // v = x + pe, layout (b, c, l)
__device__ float g_yT[BSz*Hc*Lt];     // gelu(conv + D*v), layout (b, c, l)
__device__ float g_wre[Hc*Nst], g_wim[Hc*Nst];
__device__ float g_ctre[Hc*Nst], g_ctim[Hc*Nst];  // 2*Ct folded in
__device__ float g_emb[3*16*CH3];     // [axis][pos][k]

// ---------------- posenc tables ----------------
__global__ void prep_emb_kernel() {
    int idx = blockIdx.x * blockDim.x + threadIdx.x;
    if (idx >= 3*16*CH3) return;
    int k   = idx % CH3;
    int pos = (idx / CH3) % 16;
    int i   = k >> 1;
    float freq = expf(-logf(10000.0f) * (float)(2*i) / (float)CH3);
    float arg  = (float)pos * freq;
    g_emb[idx] = (k & 1) ? cosf(arg) : sinf(arg);
}

// ---------------- discretize: w = exp(dt*A), Ct' = 2*C*(w-1)/A ----------------
__global__ void prep_ct_kernel(const float* __restrict__ log_dt,
                               const float* __restrict__ Are, const float* __restrict__ Aim,
                               const float* __restrict__ Cre, const float* __restrict__ Cim) {
    int idx = blockIdx.x * blockDim.x + threadIdx.x;
    if (idx >= Hc*Nst) return;
    int c = idx >> 6;
    float dt  = expf(log_dt[c]);
    float ar  = Are[idx], ai = Aim[idx];
    float dar = dt*ar, dai = dt*ai;
    float er  = expf(dar);
    float sn, cs; sincosf(dai, &sn, &cs);
    float wr = er*cs, wi = er*sn;
    g_wre[idx] = wr; g_wim[idx] = wi;
    // q = (w - 1)/A   (complex division)
    float nr = wr - 1.0f, ni = wi;
    float inv = 1.0f / (ar*ar + ai*ai);
    float qr = (nr*ar + ni*ai) * inv;
    float qi = (ni*ar - nr*ai) * inv;
    float cr = Cre[idx], ci = Cim[idx];
    g_ctre[idx] = 2.0f*(cr*qr - ci*qi);   // fold the 2*Re(...) factor here
    g_ctim[idx] = 2.0f*(cr*qi + ci*qr);
}

// ---------------- v = x + posenc ----------------
__global__ void v_kernel(const float* __restrict__ x) {
    int i4 = blockIdx.x * blockDim.x + threadIdx.x;
    if (i4 >= BSz*Hc*Lt/4) return;
    int l4 = i4 & (Lt/4 - 1);
    int c  = (i4 >> 10) & (Hc - 1);
    int l  = l4 << 2;
    int lw = l & 15, lh = (l >> 4) & 15, lf = l >> 8;
    float4 xv = ((const float4*)x)[i4];
    float4 pv;
    if (c < CH3) {                       // x-axis (f): constant over 16*16 inner
        float e = g_emb[lf*CH3 + c];
        pv = make_float4(e, e, e, e);
    } else if (c < 2*CH3) {              // y-axis (h): constant over inner 16
        float e = g_emb[(16 + lh)*CH3 + (c - CH3)];
        pv = make_float4(e, e, e, e);
    } else {                             // z-axis (w): varies per l, period 16
        int k = c - 2*CH3;
        const float* ez = g_emb + 32*CH3 + k;
        pv = make_float4(ez[(lw+0)*CH3], ez[(lw+1)*CH3], ez[(lw+2)*CH3], ez[(lw+3)*CH3]);
    }
    ((float4*)g_v)[i4] = make_float4(xv.x+pv.x, xv.y+pv.y, xv.z+pv.z, xv.w+pv.w);
}

// ---------------- diagonal SSM recurrence + skip + gelu ----------------
// one warp per (b, c); lane owns states n=lane and n=lane+32
__global__ __launch_bounds__(256) void ssm_kernel(const float* __restrict__ D) {
    int gtid = blockIdx.x * blockDim.x + threadIdx.x;
    int wid  = gtid >> 5;
    int lane = gtid & 31;
    int c    = wid & (Hc - 1);
    int n0 = (c << 6) + lane, n1 = n0 + 32;

    float wr0 = g_wre[n0],  wi0 = g_wim[n0];
    float wr1 = g_wre[n1],  wi1 = g_wim[n1];
    float cr0 = g_ctre[n0], ci0 = g_ctim[n0];
    float cr1 = g_ctre[n1], ci1 = g_ctim[n1];
    float dc  = D[c];

    const float4* vp = (const float4*)(g_v + (size_t)wid * Lt);
    float*        yp = g_yT + (size_t)wid * Lt;

    float sr0 = 0.f, si0 = 0.f, sr1 = 0.f, si1 = 0.f;
    float hold = 0.f;

    #pragma unroll 2
    for (int l4 = 0; l4 < Lt/4; ++l4) {
        float4 vv4 = vp[l4];
        #pragma unroll
        for (int j = 0; j < 4; ++j) {
            float vv = (j == 0) ? vv4.x : (j == 1) ? vv4.y : (j == 2) ? vv4.z : vv4.w;
            // s = w*s + v   (complex, v real)
            float t0   = fmaf(-wi0, si0, vv);
            float u0   = wr0 * si0;
            float t1   = fmaf(-wi1, si1, vv);
            float u1   = wr1 * si1;
            float nsr0 = fmaf(wr0, sr0, t0);
            float nsi0 = fmaf(wi0, sr0, u0);
            float nsr1 = fmaf(wr1, sr1, t1);
            float nsi1 = fmaf(wi1, sr1, u1);
            sr0 = nsr0; si0 = nsi0; sr1 = nsr1; si1 = nsi1;
            // partial of 2*Re(Ct . s) over this lane's two states
            float p = fmaf(cr1, sr1, fmaf(-ci1, si1, fmaf(cr0, sr0, -ci0 * si0)));
            #pragma unroll
            for (int off = 16; off; off >>= 1)
                p += __shfl_xor_sync(0xffffffffu, p, off);
            float res = fmaf(dc, vv, p);               // + D * v skip
            // gelu (tanh approx, overflow-safe via exp form)
            float a2 = 1.5957691216057308f * fmaf(0.044715f * res, res * res, res); // 2*sqrt(2/pi)*(x+0.044715x^3)
            float e  = __expf(a2);
            float th = 1.0f - __fdividef(2.0f, e + 1.0f);
            float g  = 0.5f * res * (1.0f + th);
            int li = (l4 << 2) + j;
            if (lane == (li & 31)) hold = g;           // round-robin staging
        }
        if ((l4 & 7) == 7)                              // every 32 steps: coalesced store
            yp[(l4 << 2) - 28 + lane] = hold;
    }
}

// ---------------- out[b,o,l] = sum_c W[c,o] * yT[b,c,l] + bias[o] ----------------
// tile: 64 (o) x 128 (l), BK=16, 256 threads, 4x8 microtile
__global__ __launch_bounds__(256) void gemm_kernel(const float* __restrict__ W,
                                                   const float* __restrict__ bias,
                                                   float* __restrict__ out) {
    __shared__ float Ws[16][64];
    __shared__ float Ys[16][128];
    int b  = blockIdx.z;
    int oo = blockIdx.y << 6;
    int ll = blockIdx.x << 7;
    int tid = threadIdx.x;
    int tl = tid & 15;        // l micro: tl*8
    int to = tid >> 4;        // o micro: to*4

    float acc[4][8];
    #pragma unroll
    for (int i = 0; i < 4; ++i)
        #pragma unroll
        for (int j = 0; j < 8; ++j) acc[i][j] = 0.f;

    int lwk = tid >> 4, lwo = (tid & 15) << 2;
    int lyk = tid >> 5, lyl = (tid & 31) << 2;
    const float* Yb = g_yT + (size_t)b * Hc * Lt + ll;

    for (int kk = 0; kk < Hc; kk += 16) {
        *(float4*)&Ws[lwk][lwo]     = *(const float4*)&W[(kk + lwk) * OUTc + oo + lwo];
        *(float4*)&Ys[lyk][lyl]     = *(const float4*)&Yb[(size_t)(kk + lyk) * Lt + lyl];
        *(float4*)&Ys[lyk + 8][lyl] = *(const float4*)&Yb[(size_t)(kk + lyk + 8) * Lt + lyl];
        __syncthreads();
        #pragma unroll
        for (int k = 0; k < 16; ++k) {
            float4 wv = *(float4*)&Ws[k][to << 2];
            float4 y0 = *(float4*)&Ys[k][tl << 3];
            float4 y1 = *(float4*)&Ys[k][(tl << 3) + 4];
            float wa[4] = {wv.x, wv.y, wv.z, wv.w};
            float ya[8] = {y0.x, y0.y, y0.z, y0.w, y1.x, y1.y, y1.z, y1.w};
            #pragma unroll
            for (int i = 0; i < 4; ++i)
                #pragma unroll
                for (int j = 0; j < 8; ++j)
                    acc[i][j] = fmaf(wa[i], ya[j], acc[i][j]);
        }
        __syncthreads();
    }
    #pragma unroll
    for (int i = 0; i < 4; ++i) {
        int o = oo + (to << 2) + i;
        float bo = __ldg(&bias[o]);
        float* op = out + ((size_t)b * OUTc + o) * Lt + ll + (tl << 3);
        float4 r0 = make_float4(acc[i][0]+bo, acc[i][1]+bo, acc[i][2]+bo, acc[i][3]+bo);
        float4 r1 = make_float4(acc[i][4]+bo, acc[i][5]+bo, acc[i][6]+bo, acc[i][7]+bo);
        *(float4*)op       = r0;
        *(float4*)(op + 4) = r1;
    }
}

// ---------------- launch ----------------
extern "C" void kernel_launch(void* const* d_in, const int* in_sizes, int n_in,
                              void* d_out, int out_size) {
    const float* x      = (const float*)d_in[0];
    const float* log_dt = (const float*)d_in[1];
    const float* A_re   = (const float*)d_in[2];
    const float* A_im   = (const float*)d_in[3];
    const float* C_re   = (const float*)d_in[4];
    const float* C_im   = (const float*)d_in[5];
    const float* D      = (const float*)d_in[6];
    const float* W      = (const float*)d_in[7];
    const float* bias   = (const float*)d_in[8];
    float* out = (float*)d_out;

    prep_emb_kernel<<<(3*16*CH3 + 255)/256, 256>>>();
    prep_ct_kernel<<<(Hc*Nst + 255)/256, 256>>>(log_dt, A_re, A_im, C_re, C_im);
    v_kernel<<<(BSz*Hc*Lt/4 + 255)/256, 256>>>(x);
    ssm_kernel<<<(BSz*Hc*32)/256, 256>>>(D);                    // one warp per (b,c)
    gemm_kernel<<<dim3(Lt/128, OUTc/64, BSz), 256>>>(W, bias, out);
}

// round 2
// speedup vs baseline: 1.8937x; 1.8937x over previous
#include <cuda_runtime.h>
#include <math.h>

#define Hc   1024
#define Nst  64
#define Lt   4096
#define OUTc 512
#define BSz  2
#define CH3  342   // per-axis posenc channels

typedef unsigned long long u64;

// ---------------- f32x2 packed math (sm_103a FFMA2 path) ----------------
__device__ __forceinline__ u64 f2fma(u64 a, u64 b, u64 c) {
    u64 d; asm("fma.rn.f32x2 %0,%1,%2,%3;" : "=l"(d) : "l"(a), "l"(b), "l"(c)); return d;
}
__device__ __forceinline__ u64 f2mul(u64 a, u64 b) {
    u64 d; asm("mul.rn.f32x2 %0,%1,%2;" : "=l"(d) : "l"(a), "l"(b)); return d;
}
__device__ __forceinline__ u64 f2add(u64 a, u64 b) {
    u64 d; asm("add.rn.f32x2 %0,%1,%2;" : "=l"(d) : "l"(a), "l"(b)); return d;
}
__device__ __forceinline__ u64 f2pack(float lo, float hi) {
    u64 d; asm("mov.b64 %0,{%1,%2};" : "=l"(d) : "f"(lo), "f"(hi)); return d;
}
__device__ __forceinline__ float2 f2unpack(u64 v) {
    float2 r; asm("mov.b64 {%0,%1},%2;" : "=f"(r.x), "=f"(r.y) : "l"(v)); return r;
}

// ---------------- scratch ----------------
__device__ float g_v [BSz*Hc*Lt];     // v = x + pe, layout (b, c, l)
__device__ float g_yT[BSz*Hc*Lt];     // gelu(conv + D*v), layout (b, c, l)
__device__ float g_wre[Hc*Nst], g_wim[Hc*Nst];
__device__ float g_ctre[Hc*Nst], g_ctim[Hc*Nst];
__device__ float g_emb[3*16*CH3];     // [axis][pos][k]

// ---------------- posenc tables ----------------
__global__ void prep_emb_kernel() {
    int idx = blockIdx.x * blockDim.x + threadIdx.x;
    if (idx >= 3*16*CH3) return;
    int k   = idx % CH3;
    int pos = (idx / CH3) % 16;
    int i   = k >> 1;
    float freq = expf(-logf(10000.0f) * (float)(2*i) / (float)CH3);
    float arg  = (float)pos * freq;
    g_emb[idx] = (k & 1) ? cosf(arg) : sinf(arg);
}

// ---------------- discretize: w = exp(dt*A), Ct' = 2*C*(w-1)/A ----------------
__global__ void prep_ct_kernel(const float* __restrict__ log_dt,
                               const float* __restrict__ Are, const float* __restrict__ Aim,
                               const float* __restrict__ Cre, const float* __restrict__ Cim) {
    int idx = blockIdx.x * blockDim.x + threadIdx.x;
    if (idx >= Hc*Nst) return;
    int c = idx >> 6;
    float dt  = expf(log_dt[c]);
    float ar  = Are[idx], ai = Aim[idx];
    float dar = dt*ar, dai = dt*ai;
    float er  = expf(dar);
    float sn, cs; sincosf(dai, &sn, &cs);
    float wr = er*cs, wi = er*sn;
    g_wre[idx] = wr; g_wim[idx] = wi;
    float nr = wr - 1.0f, ni = wi;
    float inv = 1.0f / (ar*ar + ai*ai);
    float qr = (nr*ar + ni*ai) * inv;
    float qi = (ni*ar - nr*ai) * inv;
    float cr = Cre[idx], ci = Cim[idx];
    g_ctre[idx] = 2.0f*(cr*qr - ci*qi);
    g_ctim[idx] = 2.0f*(cr*qi + ci*qr);
}

// ---------------- v = x + posenc ----------------
__global__ void v_kernel(const float* __restrict__ x) {
    int i4 = blockIdx.x * blockDim.x + threadIdx.x;
    if (i4 >= BSz*Hc*Lt/4) return;
    int l4 = i4 & (Lt/4 - 1);
    int c  = (i4 >> 10) & (Hc - 1);
    int l  = l4 << 2;
    int lw = l & 15, lh = (l >> 4) & 15, lf = l >> 8;
    float4 xv = ((const float4*)x)[i4];
    float4 pv;
    if (c < CH3) {
        float e = g_emb[lf*CH3 + c];
        pv = make_float4(e, e, e, e);
    } else if (c < 2*CH3) {
        float e = g_emb[(16 + lh)*CH3 + (c - CH3)];
        pv = make_float4(e, e, e, e);
    } else {
        int k = c - 2*CH3;
        const float* ez = g_emb + 32*CH3 + k;
        pv = make_float4(ez[(lw+0)*CH3], ez[(lw+1)*CH3], ez[(lw+2)*CH3], ez[(lw+3)*CH3]);
    }
    ((float4*)g_v)[i4] = make_float4(xv.x+pv.x, xv.y+pv.y, xv.z+pv.z, xv.w+pv.w);
}

// ---------------- diagonal SSM recurrence + skip + gelu ----------------
// one warp per (b, c); lane owns packed states {n=lane, n=lane+32} as f32x2
#define RPAD 68   // words per reduce row (32 float2 = 64 words + 4 pad)

__global__ __launch_bounds__(32) void ssm_kernel(const float* __restrict__ D) {
    __shared__ float ps[32*RPAD];
    int wid  = blockIdx.x;          // b*Hc + c
    int lane = threadIdx.x;
    int c    = wid & (Hc - 1);
    int n0   = (c << 6) + lane;

    u64 Wr  = f2pack( g_wre[n0],   g_wre[n0+32]);
    u64 Wi  = f2pack( g_wim[n0],   g_wim[n0+32]);
    u64 Win = f2pack(-g_wim[n0],  -g_wim[n0+32]);
    u64 Cr  = f2pack( g_ctre[n0],  g_ctre[n0+32]);
    u64 Cin = f2pack(-g_ctim[n0], -g_ctim[n0+32]);
    u64 Dc  = f2pack( D[c]*0.03125f, 0.0f);   // D/32: each lane contributes 1/32 of skip

    const float4* vp = (const float4*)(g_v + (size_t)wid * Lt);
    float*        yp = g_yT + (size_t)wid * Lt;

    u64 Sr = 0ull, Si = 0ull;   // {0.f, 0.f}

    for (int base = 0; base < Lt; base += 32) {
        float4 va[8];
        #pragma unroll
        for (int q = 0; q < 8; ++q) va[q] = vp[(base >> 2) + q];

        #pragma unroll
        for (int q = 0; q < 8; ++q) {
            #pragma unroll
            for (int j = 0; j < 4; ++j) {
                float vv = (j == 0) ? va[q].x : (j == 1) ? va[q].y : (j == 2) ? va[q].z : va[q].w;
                u64 vv2 = f2pack(vv, vv);
                u64 t   = f2fma(Win, Si, vv2);       // v - wi*si
                u64 u   = f2mul(Wr,  Si);            // wr*si
                u64 nSr = f2fma(Wr,  Sr, t);         // wr*sr - wi*si + v
                Si      = f2fma(Wi,  Sr, u);         // wi*sr + wr*si
                Sr      = nSr;
                u64 p2  = f2fma(Cin, Si, f2mul(Cr, Sr));  // cr*sr - ci*si (per packed state)
                p2      = f2fma(Dc,  vv2, p2);            // + (D/32)*v in lo half
                *(u64*)&ps[(q*4 + j)*RPAD + (lane << 1)] = p2;
            }
        }
        __syncwarp();
        // lane t reduces row t (its timestep): 16x LDS.128, packed adds
        const ulonglong2* row = (const ulonglong2*)&ps[lane * RPAD];
        u64 a0 = 0ull, a1 = 0ull;
        #pragma unroll
        for (int q = 0; q < 16; ++q) {
            ulonglong2 rr = row[q];
            a0 = f2add(a0, rr.x);
            a1 = f2add(a1, rr.y);
        }
        float2 sf = f2unpack(f2add(a0, a1));
        float s = sf.x + sf.y;
        // gelu (tanh approx), overflow-safe
        float a2 = 1.5957691216057308f * fmaf(0.044715f * s, s * s, s);
        float e  = __expf(a2);
        float th = 1.0f - __fdividef(2.0f, e + 1.0f);
        yp[base + lane] = 0.5f * s * (1.0f + th);
        __syncwarp();
    }
}

// ---------------- out[b,o,l] = sum_c W[c,o] * yT[b,c,l] + bias[o] ----------------
// 128(o) x 128(l) tile, BK=8, 256 threads, 8x8 microtile, reg->smem double buffer
__global__ __launch_bounds__(256) void gemm_kernel(const float* __restrict__ W,
                                                   const float* __restrict__ bias,
                                                   float* __restrict__ out) {
    __shared__ float Ws[2][8][128];
    __shared__ float Ys[2][8][128];
    int b  = blockIdx.z;
    int oo = blockIdx.y << 7;
    int ll = blockIdx.x << 7;
    int tid = threadIdx.x;
    int tx = tid & 15, ty = tid >> 4;
    int lr = tid >> 5;              // load row 0..7
    int lc = (tid & 31) << 2;       // load col 0..124

    const float* Wp = W + (size_t)lr * OUTc + oo + lc;
    const float* Yp = g_yT + ((size_t)b * Hc + lr) * Lt + ll + lc;

    float4 wreg = *(const float4*)Wp;
    float4 yreg = *(const float4*)Yp;

    float acc[8][8];
    #pragma unroll
    for (int i = 0; i < 8; ++i)
        #pragma unroll
        for (int j = 0; j < 8; ++j) acc[i][j] = 0.f;

    int buf = 0;
    for (int kk = 0; kk < Hc; kk += 8) {
        *(float4*)&Ws[buf][lr][lc] = wreg;
        *(float4*)&Ys[buf][lr][lc] = yreg;
        __syncthreads();
        if (kk + 8 < Hc) {
            wreg = *(const float4*)(Wp + (size_t)(kk + 8) * OUTc);
            yreg = *(const float4*)(Yp + (size_t)(kk + 8) * Lt);
        }
        #pragma unroll
        for (int k = 0; k < 8; ++k) {
            float4 w0 = *(float4*)&Ws[buf][k][ty << 2];
            float4 w1 = *(float4*)&Ws[buf][k][(ty << 2) + 64];
            float4 y0 = *(float4*)&Ys[buf][k][tx << 2];
            float4 y1 = *(float4*)&Ys[buf][k][(tx << 2) + 64];
            float wa[8] = {w0.x, w0.y, w0.z, w0.w, w1.x, w1.y, w1.z, w1.w};
            float ya[8] = {y0.x, y0.y, y0.z, y0.w, y1.x, y1.y, y1.z, y1.w};
            #pragma unroll
            for (int i = 0; i < 8; ++i)
                #pragma unroll
                for (int j = 0; j < 8; ++j)
                    acc[i][j] = fmaf(wa[i], ya[j], acc[i][j]);
        }
        buf ^= 1;
    }

    #pragma unroll
    for (int i = 0; i < 8; ++i) {
        int o = oo + (ty << 2) + ((i < 4) ? i : 60 + i);   // i>=4 -> +64+(i-4)
        float bo = __ldg(&bias[o]);
        float* op = out + ((size_t)b * OUTc + o) * Lt + ll + (tx << 2);
        float4 r0 = make_float4(acc[i][0]+bo, acc[i][1]+bo, acc[i][2]+bo, acc[i][3]+bo);
        float4 r1 = make_float4(acc[i][4]+bo, acc[i][5]+bo, acc[i][6]+bo, acc[i][7]+bo);
        *(float4*)op        = r0;
        *(float4*)(op + 64) = r1;
    }
}

// ---------------- launch ----------------
extern "C" void kernel_launch(void* const* d_in, const int* in_sizes, int n_in,
                              void* d_out, int out_size) {
    const float* x      = (const float*)d_in[0];
    const float* log_dt = (const float*)d_in[1];
    const float* A_re   = (const float*)d_in[2];
    const float* A_im   = (const float*)d_in[3];
    const float* C_re   = (const float*)d_in[4];
    const float* C_im   = (const float*)d_in[5];
    const float* D      = (const float*)d_in[6];
    const float* W      = (const float*)d_in[7];
    const float* bias   = (const float*)d_in[8];
    float* out = (float*)d_out;

    prep_emb_kernel<<<(3*16*CH3 + 255)/256, 256>>>();
    prep_ct_kernel<<<(Hc*Nst + 255)/256, 256>>>(log_dt, A_re, A_im, C_re, C_im);
    v_kernel<<<(BSz*Hc*Lt/4 + 255)/256, 256>>>(x);
    ssm_kernel<<<BSz*Hc, 32>>>(D);                               // one warp per (b,c)
    gemm_kernel<<<dim3(Lt/128, OUTc/128, BSz), 256>>>(W, bias, out);
}